// round 9
// baseline (speedup 1.0000x reference)
#include <cuda_runtime.h>
#include <cuda_fp16.h>
#include <cuda_bf16.h>

// AffineAugment: per-batch rigid affine warp [B,H,W,D,1] fp32, trilinear, zero fill.
// B=4, H=W=D=192.
// Kernel 1 builds tab[v] = half2(x[v], x[v+1 in z, edge-dup]) -> any z gives one
// aligned 4B load with both z-taps (halves gather LDG count).
// Kernel 2 gathers with 4 LDGs/voxel; mats live in __constant__ (LDC, no L1tex).

#define BB  4
#define HH  192
#define WW  192
#define DD  192
#define NVOX (BB * HH * WW * DD)      // 28,311,552

__device__ static __half2 g_tab[NVOX];   // 113 MB static scratch (allowed)
__constant__ float c_mats[BB * 12];

// ---- kernel 1: build the z-pair fp16 table -------------------------------
__global__ void __launch_bounds__(256)
build_tab_kernel(const float* __restrict__ x)
{
    const int t   = blockIdx.x * blockDim.x + threadIdx.x;   // NVOX/4 threads
    const int z4  = (t % (DD / 4)) * 4;
    const int row = t / (DD / 4);

    const float* __restrict__ rp = x + (size_t)row * DD;
    const float4 v = *(const float4*)(rp + z4);

    // neighbor v.x of lane+1 == x[z4+4] when same row; boundaries handled below
    const float sh = __shfl_down_sync(0xffffffffu, v.x, 1);
    float nxt;
    if (z4 == DD - 4)                    nxt = v.w;                // row end: dup
    else if ((threadIdx.x & 31) == 31)   nxt = __ldg(rp + z4 + 4); // warp edge
    else                                 nxt = sh;

    union { uint4 u; __half2 h[4]; } w;
    w.h[0] = __floats2half2_rn(v.x, v.y);
    w.h[1] = __floats2half2_rn(v.y, v.z);
    w.h[2] = __floats2half2_rn(v.z, v.w);
    w.h[3] = __floats2half2_rn(v.w, nxt);

    *(uint4*)(g_tab + (size_t)row * DD + z4) = w.u;
}

// ---- kernel 2: gather ----------------------------------------------------
// block = (192, 2): two z-rows (j, j+1); grid = (WW/2, HH, BB). 384 thr -> occ 94%.
__global__ void __launch_bounds__(384)
affine_warp_kernel(float* __restrict__ out)
{
    const int k = threadIdx.x;
    const int j = blockIdx.x * 2 + threadIdx.y;
    const int i = blockIdx.y;
    const int b = blockIdx.z;

    const float* M = c_mats + b * 12;    // uniform LDC reads, no L1tex traffic
    const float fi = (float)i, fj = (float)j, fk = (float)k;
    const float lx = fmaf(M[0], fi, fmaf(M[1], fj, fmaf(M[ 2], fk, M[ 3])));
    const float ly = fmaf(M[4], fi, fmaf(M[5], fj, fmaf(M[ 6], fk, M[ 7])));
    const float lz = fmaf(M[8], fi, fmaf(M[9], fj, fmaf(M[10], fk, M[11])));

    // all dims equal -> single min/max window test (matches per-axis check)
    const float lo = fminf(fminf(lx, ly), lz);
    const float hi = fmaxf(fmaxf(lx, ly), lz);

    float v = 0.0f;
    if ((lo >= 0.0f) & (hi <= (float)(HH - 1))) {
        const int ix0 = __float2int_rd(lx);
        const int iy0 = __float2int_rd(ly);
        const int iz0 = __float2int_rd(lz);
        const float tx = lx - (float)ix0;
        const float ty = ly - (float)iy0;
        const float tz = lz - (float)iz0;

        // clamped +1 steps along x/y (z handled inside the packed pair)
        const int ox = (ix0 < HH - 1) ? (WW * DD) : 0;
        const int oy = (iy0 < WW - 1) ? DD        : 0;

        const __half2* __restrict__ p =
            g_tab + (size_t)b * (HH * WW * DD) + (ix0 * WW + iy0) * DD + iz0;

        const float2 f00 = __half22float2(__ldg(p));
        const float2 f01 = __half22float2(__ldg(p + oy));
        const float2 f10 = __half22float2(__ldg(p + ox));
        const float2 f11 = __half22float2(__ldg(p + ox + oy));

        const float c00 = fmaf(tz, f00.y - f00.x, f00.x);
        const float c01 = fmaf(tz, f01.y - f01.x, f01.x);
        const float c10 = fmaf(tz, f10.y - f10.x, f10.x);
        const float c11 = fmaf(tz, f11.y - f11.x, f11.x);
        const float c0  = fmaf(ty, c01 - c00, c00);
        const float c1  = fmaf(ty, c11 - c10, c10);
        v = fmaf(tx, c1 - c0, c0);
    }

    __stcs(out + ((size_t)((b * HH + i) * WW + j) * DD + k), v);
}

extern "C" void kernel_launch(void* const* d_in, const int* in_sizes, int n_in,
                              void* d_out, int out_size)
{
    const float* x    = (const float*)d_in[0];
    const float* mats = (const float*)d_in[1];
    float* out        = (float*)d_out;

    // mats (48 floats) -> __constant__; D2D async copy is graph-capturable
    cudaMemcpyToSymbolAsync(c_mats, mats, BB * 12 * sizeof(float), 0,
                            cudaMemcpyDeviceToDevice, 0);

    // 1) rebuild pair table every call (deterministic)
    const int conv_threads = 256;
    const int conv_blocks  = (NVOX / 4) / conv_threads;   // 27,648 exact
    build_tab_kernel<<<conv_blocks, conv_threads>>>(x);

    // 2) gather
    dim3 grid(WW / 2, HH, BB);
    dim3 block(DD, 2);
    affine_warp_kernel<<<grid, block>>>(out);
}

// round 11
// speedup vs baseline: 1.3454x; 1.3454x over previous
#include <cuda_runtime.h>
#include <cuda_bf16.h>

// AffineAugment: per-batch rigid affine warp [B,H,W,D,1] fp32, trilinear, zero fill.
// B=4, H=W=D=192.
// Fused single kernel (no precompute tax). Mapping: one thread = one output
// voxel; block = one z-row (192 threads); grid = (j, i, b) -> warp spans 32
// consecutive z (minimal cache lines per tap LDG; kernel is L1-wavefront-bound).
// mats live in __constant__ (uniform LDC, zero L1tex traffic). Warp-coherent
// `valid` branch skips all 8 tap loads in the zero-fill border.

#define BB  4
#define HH  192
#define WW  192
#define DD  192

__constant__ float c_mats[BB * 12];

__global__ void __launch_bounds__(192)
affine_warp_kernel(const float* __restrict__ x,
                   float* __restrict__ out)
{
    const int k = threadIdx.x;
    const int j = blockIdx.x;
    const int i = blockIdx.y;
    const int b = blockIdx.z;

    const float* M = c_mats + b * 12;    // uniform constant-cache reads
    const float fi = (float)i, fj = (float)j, fk = (float)k;
    const float lx = fmaf(M[0], fi, fmaf(M[1], fj, fmaf(M[ 2], fk, M[ 3])));
    const float ly = fmaf(M[4], fi, fmaf(M[5], fj, fmaf(M[ 6], fk, M[ 7])));
    const float lz = fmaf(M[8], fi, fmaf(M[9], fj, fmaf(M[10], fk, M[11])));

    // all dims equal (192) -> single window test == per-axis bounds test
    const float lo = fminf(fminf(lx, ly), lz);
    const float hi = fmaxf(fmaxf(lx, ly), lz);

    float v = 0.0f;
    if ((lo >= 0.0f) & (hi <= (float)(HH - 1))) {
        const int ix0 = __float2int_rd(lx);
        const int iy0 = __float2int_rd(ly);
        const int iz0 = __float2int_rd(lz);
        const float tx = lx - (float)ix0;
        const float ty = ly - (float)iy0;
        const float tz = lz - (float)iz0;

        // clamped +1 steps (0 at top edge -> reads same voxel; weight handles it)
        const int ox = (ix0 < HH - 1) ? (WW * DD) : 0;
        const int oy = (iy0 < WW - 1) ? DD        : 0;
        const int oz = (iz0 < DD - 1) ? 1         : 0;

        const float* __restrict__ p0 =
            x + (size_t)b * (HH * WW * DD) + (ix0 * WW + iy0) * DD + iz0;
        const float* __restrict__ p1 = p0 + ox;      // +x row
        const float* __restrict__ q0 = p0 + oy;      // +y row
        const float* __restrict__ q1 = p1 + oy;      // +x+y row

        const float c000 = __ldg(p0);
        const float c001 = __ldg(p0 + oz);
        const float c010 = __ldg(q0);
        const float c011 = __ldg(q0 + oz);
        const float c100 = __ldg(p1);
        const float c101 = __ldg(p1 + oz);
        const float c110 = __ldg(q1);
        const float c111 = __ldg(q1 + oz);

        const float c00 = fmaf(tz, c001 - c000, c000);
        const float c01 = fmaf(tz, c011 - c010, c010);
        const float c10 = fmaf(tz, c101 - c100, c100);
        const float c11 = fmaf(tz, c111 - c110, c110);
        const float c0  = fmaf(ty, c01 - c00, c00);
        const float c1  = fmaf(ty, c11 - c10, c10);
        v = fmaf(tx, c1 - c0, c0);
    }

    __stcs(out + ((size_t)((b * HH + i) * WW + j) * DD + k), v);
}

extern "C" void kernel_launch(void* const* d_in, const int* in_sizes, int n_in,
                              void* d_out, int out_size)
{
    const float* x    = (const float*)d_in[0];
    const float* mats = (const float*)d_in[1];
    float* out        = (float*)d_out;

    // mats (48 floats) -> __constant__; async D2D copy is graph-capturable
    cudaMemcpyToSymbolAsync(c_mats, mats, BB * 12 * sizeof(float), 0,
                            cudaMemcpyDeviceToDevice);

    dim3 grid(WW, HH, BB);     // (j, i, b)
    dim3 block(DD);            // k
    affine_warp_kernel<<<grid, block>>>(x, out);
}

// round 12
// speedup vs baseline: 1.3513x; 1.0044x over previous
#include <cuda_runtime.h>
#include <cuda_bf16.h>

// AffineAugment: per-batch rigid affine warp [B,H,W,D,1] fp32, trilinear, zero fill.
// B=4, H=W=D=192.
// Fused single kernel. One thread = one output voxel; block = one z-row (192
// threads); grid = (j, i, b) -> warp spans 32 consecutive z (minimal lines per
// tap LDG). mats in __constant__ (uniform LDC). Warp-coherent `valid` branch
// skips the fill border.
// NEW: interior fast path — when hi < 191.0f, every +1 step is a compile-time
// constant, so all 8 taps are LDG [base+imm] with ONE address computation.
// (A clamped offset can only be 0 when a coord floors to exactly 191.)

#define BB  4
#define HH  192
#define WW  192
#define DD  192

__constant__ float c_mats[BB * 12];

__global__ void __launch_bounds__(192)
affine_warp_kernel(const float* __restrict__ x,
                   float* __restrict__ out)
{
    const int k = threadIdx.x;
    const int j = blockIdx.x;
    const int i = blockIdx.y;
    const int b = blockIdx.z;

    const float* M = c_mats + b * 12;    // uniform constant-cache reads
    const float fi = (float)i, fj = (float)j, fk = (float)k;
    const float lx = fmaf(M[0], fi, fmaf(M[1], fj, fmaf(M[ 2], fk, M[ 3])));
    const float ly = fmaf(M[4], fi, fmaf(M[5], fj, fmaf(M[ 6], fk, M[ 7])));
    const float lz = fmaf(M[8], fi, fmaf(M[9], fj, fmaf(M[10], fk, M[11])));

    // all dims equal (192) -> single window test == per-axis bounds test
    const float lo = fminf(fminf(lx, ly), lz);
    const float hi = fmaxf(fmaxf(lx, ly), lz);

    float v = 0.0f;
    if ((lo >= 0.0f) & (hi <= (float)(HH - 1))) {
        const int ix0 = __float2int_rd(lx);
        const int iy0 = __float2int_rd(ly);
        const int iz0 = __float2int_rd(lz);
        const float tx = lx - (float)ix0;
        const float ty = ly - (float)iy0;
        const float tz = lz - (float)iz0;

        const float* __restrict__ p0 =
            x + (size_t)b * (HH * WW * DD) + (ix0 * WW + iy0) * DD + iz0;

        float c000, c001, c010, c011, c100, c101, c110, c111;

        if (hi < (float)(HH - 1)) {
            // interior: ix0,iy0,iz0 <= 190 -> +1 steps are constants ->
            // all taps are immediate-offset loads off ONE base pointer.
            c000 = __ldg(p0);
            c001 = __ldg(p0 + 1);
            c010 = __ldg(p0 + DD);
            c011 = __ldg(p0 + DD + 1);
            c100 = __ldg(p0 + WW * DD);
            c101 = __ldg(p0 + WW * DD + 1);
            c110 = __ldg(p0 + WW * DD + DD);
            c111 = __ldg(p0 + WW * DD + DD + 1);
        } else {
            // boundary sliver: some coord == 191 exactly -> clamp steps to 0
            const int ox = (ix0 < HH - 1) ? (WW * DD) : 0;
            const int oy = (iy0 < WW - 1) ? DD        : 0;
            const int oz = (iz0 < DD - 1) ? 1         : 0;
            c000 = __ldg(p0);
            c001 = __ldg(p0 + oz);
            c010 = __ldg(p0 + oy);
            c011 = __ldg(p0 + oy + oz);
            c100 = __ldg(p0 + ox);
            c101 = __ldg(p0 + ox + oz);
            c110 = __ldg(p0 + ox + oy);
            c111 = __ldg(p0 + ox + oy + oz);
        }

        const float c00 = fmaf(tz, c001 - c000, c000);
        const float c01 = fmaf(tz, c011 - c010, c010);
        const float c10 = fmaf(tz, c101 - c100, c100);
        const float c11 = fmaf(tz, c111 - c110, c110);
        const float c0  = fmaf(ty, c01 - c00, c00);
        const float c1  = fmaf(ty, c11 - c10, c10);
        v = fmaf(tx, c1 - c0, c0);
    }

    __stcs(out + ((size_t)((b * HH + i) * WW + j) * DD + k), v);
}

extern "C" void kernel_launch(void* const* d_in, const int* in_sizes, int n_in,
                              void* d_out, int out_size)
{
    const float* x    = (const float*)d_in[0];
    const float* mats = (const float*)d_in[1];
    float* out        = (float*)d_out;

    // mats (48 floats) -> __constant__; async D2D copy is graph-capturable
    cudaMemcpyToSymbolAsync(c_mats, mats, BB * 12 * sizeof(float), 0,
                            cudaMemcpyDeviceToDevice);

    dim3 grid(WW, HH, BB);     // (j, i, b)
    dim3 block(DD);            // k
    affine_warp_kernel<<<grid, block>>>(x, out);
}

// round 13
// speedup vs baseline: 1.5338x; 1.1350x over previous
#include <cuda_runtime.h>
#include <cuda_bf16.h>

// AffineAugment: per-batch rigid affine warp [B,H,W,D,1] fp32, trilinear, zero fill.
// B=4, H=W=D=192.
// Fused kernel. One thread = TWO output voxels: (i,j,k) and (i,j+96,k).
// The second location is base+constant (96*m01 etc.), and the two 8-tap
// gathers are independent -> 2x memory-level parallelism for the
// latency-bound tap chain, with zero change to per-tap warp footprint
// (warp still spans 32 consecutive z). mats in __constant__ (uniform LDC).
// Interior fast path: when hi < 191, all +1 steps are compile-time imms.

#define BB  4
#define HH  192
#define WW  192
#define DD  192
#define JSPLIT (WW / 2)   // 96

__constant__ float c_mats[BB * 12];

// one 8-tap trilinear sample; fast path when hi<191 (all offsets immediate)
__device__ __forceinline__ float sample_one(const float* __restrict__ vb,
                                            float lx, float ly, float lz)
{
    const float lo = fminf(fminf(lx, ly), lz);
    const float hi = fmaxf(fmaxf(lx, ly), lz);
    if (!((lo >= 0.0f) & (hi <= (float)(HH - 1)))) return 0.0f;

    const int ix0 = __float2int_rd(lx);
    const int iy0 = __float2int_rd(ly);
    const int iz0 = __float2int_rd(lz);
    const float tx = lx - (float)ix0;
    const float ty = ly - (float)iy0;
    const float tz = lz - (float)iz0;

    const float* __restrict__ p0 = vb + (ix0 * WW + iy0) * DD + iz0;

    float c000, c001, c010, c011, c100, c101, c110, c111;
    if (hi < (float)(HH - 1)) {
        c000 = __ldg(p0);
        c001 = __ldg(p0 + 1);
        c010 = __ldg(p0 + DD);
        c011 = __ldg(p0 + DD + 1);
        c100 = __ldg(p0 + WW * DD);
        c101 = __ldg(p0 + WW * DD + 1);
        c110 = __ldg(p0 + WW * DD + DD);
        c111 = __ldg(p0 + WW * DD + DD + 1);
    } else {
        const int ox = (ix0 < HH - 1) ? (WW * DD) : 0;
        const int oy = (iy0 < WW - 1) ? DD        : 0;
        const int oz = (iz0 < DD - 1) ? 1         : 0;
        c000 = __ldg(p0);
        c001 = __ldg(p0 + oz);
        c010 = __ldg(p0 + oy);
        c011 = __ldg(p0 + oy + oz);
        c100 = __ldg(p0 + ox);
        c101 = __ldg(p0 + ox + oz);
        c110 = __ldg(p0 + ox + oy);
        c111 = __ldg(p0 + ox + oy + oz);
    }

    const float c00 = fmaf(tz, c001 - c000, c000);
    const float c01 = fmaf(tz, c011 - c010, c010);
    const float c10 = fmaf(tz, c101 - c100, c100);
    const float c11 = fmaf(tz, c111 - c110, c110);
    const float c0  = fmaf(ty, c01 - c00, c00);
    const float c1  = fmaf(ty, c11 - c10, c10);
    return fmaf(tx, c1 - c0, c0);
}

__global__ void __launch_bounds__(192, 8)
affine_warp_kernel(const float* __restrict__ x,
                   float* __restrict__ out)
{
    const int k = threadIdx.x;
    const int j = blockIdx.x;          // 0..95 ; second voxel at j+96
    const int i = blockIdx.y;
    const int b = blockIdx.z;

    const float* M = c_mats + b * 12;
    const float fi = (float)i, fj = (float)j, fk = (float)k;
    const float lx0 = fmaf(M[0], fi, fmaf(M[1], fj, fmaf(M[ 2], fk, M[ 3])));
    const float ly0 = fmaf(M[4], fi, fmaf(M[5], fj, fmaf(M[ 6], fk, M[ 7])));
    const float lz0 = fmaf(M[8], fi, fmaf(M[9], fj, fmaf(M[10], fk, M[11])));
    // j+96 location = base + constant
    const float lx1 = fmaf(M[1], (float)JSPLIT, lx0);
    const float ly1 = fmaf(M[5], (float)JSPLIT, ly0);
    const float lz1 = fmaf(M[9], (float)JSPLIT, lz0);

    const float* __restrict__ vb = x + (size_t)b * (HH * WW * DD);

    const float v0 = sample_one(vb, lx0, ly0, lz0);
    const float v1 = sample_one(vb, lx1, ly1, lz1);

    float* __restrict__ o = out + ((size_t)((b * HH + i) * WW + j) * DD + k);
    __stcs(o, v0);
    __stcs(o + (size_t)JSPLIT * DD, v1);
}

extern "C" void kernel_launch(void* const* d_in, const int* in_sizes, int n_in,
                              void* d_out, int out_size)
{
    const float* x    = (const float*)d_in[0];
    const float* mats = (const float*)d_in[1];
    float* out        = (float*)d_out;

    cudaMemcpyToSymbolAsync(c_mats, mats, BB * 12 * sizeof(float), 0,
                            cudaMemcpyDeviceToDevice);

    dim3 grid(JSPLIT, HH, BB);   // (j half, i, b)
    dim3 block(DD);              // k
    affine_warp_kernel<<<grid, block>>>(x, out);
}

// round 14
// speedup vs baseline: 1.5977x; 1.0417x over previous
#include <cuda_runtime.h>
#include <cuda_bf16.h>

// AffineAugment: per-batch rigid affine warp [B,H,W,D,1] fp32, trilinear, zero fill.
// B=4, H=W=D=192.
// Fused kernel. One thread = FOUR output voxels: (i, j + q*48, k), q=0..3.
// Each extra location is base+constant (48*m01 etc.); the four 8-tap gathers
// are independent -> up to 32 loads in flight per thread (latency-bound kernel;
// round 13 proved 2x MLP => 13% gain with nothing saturated).
// Warp still spans 32 consecutive z per tap (proven-minimal line footprint).
// mats in __constant__; interior fast path uses immediate-offset taps.

#define BB  4
#define HH  192
#define WW  192
#define DD  192
#define JQ  (WW / 4)      // 48

__constant__ float c_mats[BB * 12];

// one 8-tap trilinear sample; fast path when hi<191 (all offsets immediate)
__device__ __forceinline__ float sample_one(const float* __restrict__ vb,
                                            float lx, float ly, float lz)
{
    const float lo = fminf(fminf(lx, ly), lz);
    const float hi = fmaxf(fmaxf(lx, ly), lz);
    if (!((lo >= 0.0f) & (hi <= (float)(HH - 1)))) return 0.0f;

    const int ix0 = __float2int_rd(lx);
    const int iy0 = __float2int_rd(ly);
    const int iz0 = __float2int_rd(lz);
    const float tx = lx - (float)ix0;
    const float ty = ly - (float)iy0;
    const float tz = lz - (float)iz0;

    const float* __restrict__ p0 = vb + (ix0 * WW + iy0) * DD + iz0;

    float c000, c001, c010, c011, c100, c101, c110, c111;
    if (hi < (float)(HH - 1)) {
        c000 = __ldg(p0);
        c001 = __ldg(p0 + 1);
        c010 = __ldg(p0 + DD);
        c011 = __ldg(p0 + DD + 1);
        c100 = __ldg(p0 + WW * DD);
        c101 = __ldg(p0 + WW * DD + 1);
        c110 = __ldg(p0 + WW * DD + DD);
        c111 = __ldg(p0 + WW * DD + DD + 1);
    } else {
        const int ox = (ix0 < HH - 1) ? (WW * DD) : 0;
        const int oy = (iy0 < WW - 1) ? DD        : 0;
        const int oz = (iz0 < DD - 1) ? 1         : 0;
        c000 = __ldg(p0);
        c001 = __ldg(p0 + oz);
        c010 = __ldg(p0 + oy);
        c011 = __ldg(p0 + oy + oz);
        c100 = __ldg(p0 + ox);
        c101 = __ldg(p0 + ox + oz);
        c110 = __ldg(p0 + ox + oy);
        c111 = __ldg(p0 + ox + oy + oz);
    }

    const float c00 = fmaf(tz, c001 - c000, c000);
    const float c01 = fmaf(tz, c011 - c010, c010);
    const float c10 = fmaf(tz, c101 - c100, c100);
    const float c11 = fmaf(tz, c111 - c110, c110);
    const float c0  = fmaf(ty, c01 - c00, c00);
    const float c1  = fmaf(ty, c11 - c10, c10);
    return fmaf(tx, c1 - c0, c0);
}

__global__ void __launch_bounds__(192)
affine_warp_kernel(const float* __restrict__ x,
                   float* __restrict__ out)
{
    const int k = threadIdx.x;
    const int j = blockIdx.x;          // 0..47 ; voxels at j + q*48
    const int i = blockIdx.y;
    const int b = blockIdx.z;

    const float* M = c_mats + b * 12;
    const float fi = (float)i, fj = (float)j, fk = (float)k;
    const float lx0 = fmaf(M[0], fi, fmaf(M[1], fj, fmaf(M[ 2], fk, M[ 3])));
    const float ly0 = fmaf(M[4], fi, fmaf(M[5], fj, fmaf(M[ 6], fk, M[ 7])));
    const float lz0 = fmaf(M[8], fi, fmaf(M[9], fj, fmaf(M[10], fk, M[11])));

    const float dxj = M[1] * (float)JQ;
    const float dyj = M[5] * (float)JQ;
    const float dzj = M[9] * (float)JQ;

    const float* __restrict__ vb = x + (size_t)b * (HH * WW * DD);

    const float v0 = sample_one(vb, lx0,            ly0,            lz0);
    const float v1 = sample_one(vb, lx0 + dxj,      ly0 + dyj,      lz0 + dzj);
    const float v2 = sample_one(vb, lx0 + 2*dxj,    ly0 + 2*dyj,    lz0 + 2*dzj);
    const float v3 = sample_one(vb, lx0 + 3*dxj,    ly0 + 3*dyj,    lz0 + 3*dzj);

    float* __restrict__ o = out + ((size_t)((b * HH + i) * WW + j) * DD + k);
    const size_t step = (size_t)JQ * DD;
    __stcs(o,            v0);
    __stcs(o + step,     v1);
    __stcs(o + 2 * step, v2);
    __stcs(o + 3 * step, v3);
}

extern "C" void kernel_launch(void* const* d_in, const int* in_sizes, int n_in,
                              void* d_out, int out_size)
{
    const float* x    = (const float*)d_in[0];
    const float* mats = (const float*)d_in[1];
    float* out        = (float*)d_out;

    cudaMemcpyToSymbolAsync(c_mats, mats, BB * 12 * sizeof(float), 0,
                            cudaMemcpyDeviceToDevice);

    dim3 grid(JQ, HH, BB);     // (j quarter, i, b)
    dim3 block(DD);            // k
    affine_warp_kernel<<<grid, block>>>(x, out);
}